// round 4
// baseline (speedup 1.0000x reference)
#include <cuda_runtime.h>
#include <cstdint>

#define BATCH 8
#define NANCH 32768
#define NCLS  81
#define NC    80          // foreground classes
#define TOPM  200
#define NMS_TH  0.45f
#define CONF_TH 0.01f
#define NCHUNK  7         // ceil(224/32) bit chunks covering TOPM=200
#define NBIN    2048

// ---------------- scratch (static device globals; no allocations) ----------
__device__ float  g_scores[(size_t)BATCH * NC * NANCH];   // masked probs, [b][c][n]
__device__ float4 g_boxes [(size_t)BATCH * NANCH];        // decoded boxes
__device__ float  g_kept  [(size_t)BATCH * NC * TOPM];    // post-NMS scores (0 if dropped)
__device__ float4 g_cand  [(size_t)BATCH * NC * TOPM];    // candidate boxes
__device__ unsigned long long g_cutoff[BATCH];            // global top-200 composite cutoff

// bin of a score in (CONF_TH, 1): 16-bit float-bit prefix, guaranteed in [0,2048)
__device__ __forceinline__ int score_bin(float v) {
    int b = (int)(__float_as_uint(v) >> 15) - 30720;
    return min(max(b, 0), NBIN - 1);
}

// ===========================================================================
// Kernel 1: softmax over 81 classes + box decode; 2 threads per row.
// Writes transposed masked scores [b][c][n] (0 if below threshold).
// ===========================================================================
__global__ void __launch_bounds__(256)
k_softmax_decode(const float* __restrict__ loc,
                 const float* __restrict__ conf,
                 const float* __restrict__ dbox)
{
    __shared__ float sm[128 * NCLS];     // 41472 B
    __shared__ float sinv[128];

    const int blk = blockIdx.x;                    // B*N/128 blocks
    const int b   = blk / (NANCH / 128);
    const int n0  = (blk % (NANCH / 128)) * 128;
    const int tid = threadIdx.x;

    const float4* src4 = reinterpret_cast<const float4*>(
        conf + ((size_t)b * NANCH + n0) * NCLS);
    float4* sm4 = reinterpret_cast<float4*>(sm);
    for (int i = tid; i < (128 * NCLS) / 4; i += 256)
        sm4[i] = src4[i];

    // box decode - threads 0..127, one row each
    if (tid < 128) {
        const int n = n0 + tid;
        float4 l = reinterpret_cast<const float4*>(loc)[(size_t)b * NANCH + n];
        float4 d = reinterpret_cast<const float4*>(dbox)[n];
        float cx = d.x + l.x * 0.1f * d.z;
        float cy = d.y + l.y * 0.1f * d.w;
        float w  = d.z * expf(l.z * 0.2f);
        float h  = d.w * expf(l.w * 0.2f);
        float x1 = cx - w * 0.5f;
        float y1 = cy - h * 0.5f;
        float4 o;
        o.x = fminf(fmaxf(x1, 0.f), 1.f);
        o.y = fminf(fmaxf(y1, 0.f), 1.f);
        o.z = fminf(fmaxf(x1 + w, 0.f), 1.f);
        o.w = fminf(fmaxf(y1 + h, 0.f), 1.f);
        g_boxes[(size_t)b * NANCH + n] = o;
    }
    __syncthreads();

    // softmax: pair (2r, 2r+1) handles row r; halves = classes [0,41) / [41,81)
    {
        const int r    = tid >> 1;
        const int half = tid & 1;
        const int c0   = half ? 41 : 0;
        const int cn   = half ? 40 : 41;
        float* row = sm + r * NCLS;

        float m = -1e30f;
        #pragma unroll 8
        for (int c = 0; c < cn; c++) m = fmaxf(m, row[c0 + c]);
        m = fmaxf(m, __shfl_xor_sync(0xFFFFFFFFu, m, 1));

        float s = 0.f;
        #pragma unroll 8
        for (int c = 0; c < cn; c++) {
            float e = expf(row[c0 + c] - m);
            row[c0 + c] = e;
            s += e;
        }
        s += __shfl_xor_sync(0xFFFFFFFFu, s, 1);
        if (!half) sinv[r] = 1.0f / s;
    }
    __syncthreads();

    // transposed masked-score writes: coalesced per class
    for (int i = tid; i < 128 * NC; i += 256) {
        const int c  = i >> 7;       // 0..79  (class c+1)
        const int rr = i & 127;
        float p = sm[rr * NCLS + (c + 1)] * sinv[rr];
        g_scores[((size_t)b * NC + c) * NANCH + (n0 + rr)] = (p > CONF_TH) ? p : 0.0f;
    }
}

// ===========================================================================
// Kernel 2: per-(b,class) exact stable top-200. Warp-aggregated (match_any)
// histogram into 2 privatized smem copies, register-resident bin selection,
// single gather pass with uint-threshold, dynamic bitonic sort, bit-matrix NMS.
// ===========================================================================
__global__ void __launch_bounds__(256)
k_topk_nms()
{
    __shared__ unsigned int s_hist[2 * NBIN];      // 2 privatized copies (16KB)
    __shared__ unsigned int psum[256];
    __shared__ unsigned long long buf[2048];
    __shared__ unsigned int s_cnt;
    __shared__ unsigned int s_thr;
    __shared__ int s_g, s_P, s_grp, s_acc;
    __shared__ float4 s_bx[TOPM];
    __shared__ float  s_area[TOPM];
    __shared__ float  s_sc[TOPM];
    __shared__ unsigned int s_sup[TOPM * NCHUNK];  // suppression bit matrix
    __shared__ unsigned int s_act[NCHUNK];
    __shared__ int s_keep[TOPM];

    const int bc   = blockIdx.x;          // b*80 + c
    const int b    = bc / NC;
    const int tid  = threadIdx.x;
    const int lane = tid & 31;
    const float* data = g_scores + (size_t)bc * NANCH;
    const float4* d4  = reinterpret_cast<const float4*>(data);

    // ---- histogram pass: match_any-aggregated atomics, 2 privatized copies ----
    for (int i = tid; i < 2 * NBIN; i += 256) s_hist[i] = 0;
    __syncthreads();
    unsigned int* hcopy = s_hist + ((tid >> 7) << 11);   // halves 0 / 1
    for (int i = tid; i < NANCH / 4; i += 256) {
        float4 v = d4[i];
        const float vs[4] = {v.x, v.y, v.z, v.w};
        #pragma unroll
        for (int j = 0; j < 4; j++) {
            float val = vs[j];
            bool pos = (val > CONF_TH);
            unsigned int act = __ballot_sync(0xFFFFFFFFu, pos);
            if (pos) {
                int bin = score_bin(val);
                unsigned int peers = __match_any_sync(act, bin);
                if (lane == __ffs(peers) - 1)
                    atomicAdd(&hcopy[bin], __popc(peers));
            }
        }
    }
    __syncthreads();

    // ---- combine copies; per-thread 8-bin group sums (register resident) ----
    unsigned int myh[8];
    {
        uint4 a0 = reinterpret_cast<const uint4*>(s_hist)[tid * 2];
        uint4 a1 = reinterpret_cast<const uint4*>(s_hist)[tid * 2 + 1];
        uint4 b0 = reinterpret_cast<const uint4*>(s_hist + NBIN)[tid * 2];
        uint4 b1 = reinterpret_cast<const uint4*>(s_hist + NBIN)[tid * 2 + 1];
        myh[0] = a0.x + b0.x; myh[1] = a0.y + b0.y;
        myh[2] = a0.z + b0.z; myh[3] = a0.w + b0.w;
        myh[4] = a1.x + b1.x; myh[5] = a1.y + b1.y;
        myh[6] = a1.z + b1.z; myh[7] = a1.w + b1.w;
        psum[tid] = myh[0] + myh[1] + myh[2] + myh[3] +
                    myh[4] + myh[5] + myh[6] + myh[7];
    }
    __syncthreads();

    if (tid == 0) {
        int acc = 0, grp = -1;
        for (int t = 255; t >= 0; t--) {
            int c = (int)psum[t];
            if (acc + c >= TOPM) { grp = t; break; }
            acc += c;
        }
        s_grp = grp; s_acc = acc; s_cnt = 0;
        if (grp < 0) s_thr = 0u;   // <200 positives: take all
    }
    __syncthreads();
    const int grp = s_grp;
    if (tid == grp) {
        int acc = s_acc, binq = grp * 8;
        for (int bb = 7; bb >= 0; bb--) {
            int cnt = (int)myh[bb];
            if (acc + cnt >= TOPM) { binq = grp * 8 + bb; break; }
            acc += cnt;
        }
        s_thr = (unsigned int)(binq + 30720) << 15;
    }
    __syncthreads();
    const unsigned int thr = s_thr;

    // ---- gather pass: boundary superset as composite keys ----
    for (int i = tid; i < NANCH / 4; i += 256) {
        float4 v = d4[i];
        const float vs[4] = {v.x, v.y, v.z, v.w};
        #pragma unroll
        for (int j = 0; j < 4; j++) {
            float val = vs[j];
            unsigned int u = __float_as_uint(val);
            if (val > 0.f && u >= thr) {
                unsigned int p = atomicAdd(&s_cnt, 1u);
                if (p < 2048) {
                    unsigned int idx = 4 * i + j;
                    buf[p] = ((unsigned long long)u << 32) |
                             (unsigned long long)(0xFFFFFFFFu - idx);
                }
            }
        }
    }
    __syncthreads();
    if (tid == 0) {
        int g = (int)min(s_cnt, 2048u);
        int P = 256;
        while (P < g) P <<= 1;
        s_g = g; s_P = P;
    }
    __syncthreads();
    const int g = s_g, P = s_P;
    for (int i = tid; i < P; i += 256) if (i >= g) buf[i] = 0ull;
    __syncthreads();

    // ---- bitonic sort, descending, dynamic size P (pow2 in [256,2048]) ----
    for (int k = 2; k <= P; k <<= 1) {
        for (int j = k >> 1; j > 0; j >>= 1) {
            for (int t = tid; t < P; t += 256) {
                int ixj = t ^ j;
                if (ixj > t) {
                    unsigned long long a = buf[t], c2 = buf[ixj];
                    bool dirDesc = ((t & k) == 0);
                    if ((a < c2) == dirDesc) { buf[t] = c2; buf[ixj] = a; }
                }
            }
            __syncthreads();
        }
    }

    // ---- materialize top-200 candidates ----
    bool val_f = false;
    if (tid < TOPM) {
        float sc; float4 bx;
        if (tid < g) {
            unsigned long long cmp = buf[tid];
            sc = __uint_as_float((unsigned int)(cmp >> 32));
            unsigned int idx = 0xFFFFFFFFu - (unsigned int)(cmp & 0xFFFFFFFFull);
            bx = g_boxes[(size_t)b * NANCH + idx];
            val_f = true;
        } else {
            sc = 0.f; bx = make_float4(0.f, 0.f, 0.f, 0.f);
        }
        s_sc[tid]   = sc;
        s_bx[tid]   = bx;
        s_area[tid] = (bx.z - bx.x) * (bx.w - bx.y);
        s_keep[tid] = 0;
    }
    {
        unsigned int bm = __ballot_sync(0xFFFFFFFFu, val_f);
        if (lane == 0 && (tid >> 5) < NCHUNK) s_act[tid >> 5] = bm;
    }
    __syncthreads();

    // ---- suppression bit matrix: bit j of row i set iff !(IoU(i,j) <= th) ----
    for (int task = tid; task < TOPM * NCHUNK; task += 256) {
        const int i     = task / NCHUNK;
        const int chunk = task % NCHUNK;
        const float4 bi = s_bx[i];
        const float  ai = s_area[i];
        unsigned int bits = 0;
        const int jmax = min(32, TOPM - chunk * 32);
        #pragma unroll 4
        for (int bb = 0; bb < jmax; bb++) {
            const int j = chunk * 32 + bb;
            float4 bj = s_bx[j];
            float xx1 = fmaxf(bi.x, bj.x);
            float yy1 = fmaxf(bi.y, bj.y);
            float xx2 = fminf(bi.z, bj.z);
            float yy2 = fminf(bi.w, bj.w);
            float inter = fmaxf(xx2 - xx1, 0.f) * fmaxf(yy2 - yy1, 0.f);
            float uni   = s_area[j] - inter + ai;
            float iou   = inter / uni;
            if (!(iou <= NMS_TH)) bits |= (1u << bb);
        }
        s_sup[task] = bits;
    }
    __syncthreads();

    // ---- greedy scan, single warp, no block barriers ----
    if (tid < 32) {
        unsigned int act = (tid < NCHUNK) ? s_act[tid] : 0u;
        for (int i = 0; i < TOPM; i++) {
            unsigned int owner_act = __shfl_sync(0xFFFFFFFFu, act, i >> 5);
            bool k = (owner_act >> (i & 31)) & 1u;
            if (k) {
                if (tid < NCHUNK) act &= ~s_sup[i * NCHUNK + tid];
                if (tid == 0) s_keep[i] = 1;
            }
        }
    }
    __syncthreads();

    if (tid < TOPM) {
        g_kept[(size_t)bc * TOPM + tid] = s_keep[tid] ? s_sc[tid] : 0.f;
        g_cand[(size_t)bc * TOPM + tid] = s_bx[tid];
    }
}

// ===========================================================================
// Kernel 3: per-batch global top-200 composite cutoff over 16000 kept scores.
// ===========================================================================
__global__ void __launch_bounds__(256)
k_global_cutoff()
{
    __shared__ unsigned int hist[NBIN];
    __shared__ unsigned int psum[256];
    __shared__ unsigned long long buf[2048];
    __shared__ unsigned int s_cnt;
    __shared__ int s_bin, s_g, s_P;

    const int b    = blockIdx.x;
    const int tid  = threadIdx.x;
    const int lane = tid & 31;
    const int NTOT = NC * TOPM;          // 16000
    const float* data = g_kept + (size_t)b * NTOT;
    const float4* d4  = reinterpret_cast<const float4*>(data);

    for (int i = tid; i < NBIN; i += 256) hist[i] = 0;
    __syncthreads();
    for (int i = tid; i < NTOT / 4; i += 256) {
        float4 v = d4[i];
        const float vs[4] = {v.x, v.y, v.z, v.w};
        #pragma unroll
        for (int j = 0; j < 4; j++) {
            float val = vs[j];
            bool pos = (val > 0.f);
            unsigned int act = __ballot_sync(0xFFFFFFFFu, pos);
            if (pos) {
                int bin = score_bin(val);
                unsigned int peers = __match_any_sync(act, bin);
                if (lane == __ffs(peers) - 1)
                    atomicAdd(&hist[bin], __popc(peers));
            }
        }
    }
    __syncthreads();
    { unsigned int s = 0;
      #pragma unroll
      for (int j = 0; j < 8; j++) s += hist[tid * 8 + j];
      psum[tid] = s; }
    __syncthreads();
    if (tid == 0) {
        int acc = 0, binq = -1;
        for (int t = 255; t >= 0; t--) {
            if (acc + (int)psum[t] >= TOPM) {
                for (int bb = t * 8 + 7; bb >= t * 8; bb--) {
                    int cnt = (int)hist[bb];
                    if (acc + cnt >= TOPM) { binq = bb; break; }
                    acc += cnt;
                }
                break;
            }
            acc += (int)psum[t];
        }
        s_bin = binq;
        s_cnt = 0;
    }
    __syncthreads();
    const int binq = s_bin;

    if (binq < 0) {                      // fewer than 200 positives: keep all
        if (tid == 0) g_cutoff[b] = 0ull;
        return;
    }
    const unsigned int thr = (unsigned int)(binq + 30720) << 15;

    for (int i = tid; i < NTOT / 4; i += 256) {
        float4 v = d4[i];
        const float vs[4] = {v.x, v.y, v.z, v.w};
        #pragma unroll
        for (int j = 0; j < 4; j++) {
            float val = vs[j];
            unsigned int u = __float_as_uint(val);
            if (val > 0.f && u >= thr) {
                unsigned int p = atomicAdd(&s_cnt, 1u);
                if (p < 2048) {
                    unsigned int idx = 4 * i + j;
                    buf[p] = ((unsigned long long)u << 32) |
                             (unsigned long long)(0xFFFFFFFFu - idx);
                }
            }
        }
    }
    __syncthreads();
    if (tid == 0) {
        int g = (int)min(s_cnt, 2048u);
        int P = 256;
        while (P < g) P <<= 1;
        s_g = g; s_P = P;
    }
    __syncthreads();
    const int g = s_g, P = s_P;
    for (int i = tid; i < P; i += 256) if (i >= g) buf[i] = 0ull;
    __syncthreads();

    for (int k = 2; k <= P; k <<= 1) {
        for (int j = k >> 1; j > 0; j >>= 1) {
            for (int t = tid; t < P; t += 256) {
                int ixj = t ^ j;
                if (ixj > t) {
                    unsigned long long a = buf[t], c2 = buf[ixj];
                    bool dirDesc = ((t & k) == 0);
                    if ((a < c2) == dirDesc) { buf[t] = c2; buf[ixj] = a; }
                }
            }
            __syncthreads();
        }
    }

    if (tid == 0)
        g_cutoff[b] = buf[TOPM - 1];
}

// ===========================================================================
// Kernel 4: output writer — zero everything, then compact survivors to front.
// ===========================================================================
__global__ void __launch_bounds__(256)
k_write(float* __restrict__ out)
{
    __shared__ unsigned int wcnt[8];
    const int c   = blockIdx.x;   // 0..80
    const int b   = blockIdx.y;
    const int tid = threadIdx.x;

    float* o = out + ((size_t)(b * NCLS + c)) * TOPM * 5;
    for (int i = tid; i < TOPM * 5; i += 256) o[i] = 0.f;
    if (c == 0) return;
    __syncthreads();

    const int c80 = c - 1;
    const size_t base = ((size_t)b * NC + c80) * TOPM;
    const unsigned long long cut = g_cutoff[b];

    float v = 0.f; bool flag = false; float4 bx = make_float4(0.f, 0.f, 0.f, 0.f);
    if (tid < TOPM) {
        v = g_kept[base + tid];
        if (v > 0.f) {
            unsigned long long comp =
                ((unsigned long long)__float_as_uint(v) << 32) |
                (unsigned long long)(0xFFFFFFFFu - (unsigned int)(c80 * TOPM + tid));
            flag = (comp >= cut);
        }
        if (flag) bx = g_cand[base + tid];
    }
    unsigned int ball = __ballot_sync(0xFFFFFFFFu, flag);
    const int wid = tid >> 5, lane = tid & 31;
    if (lane == 0) wcnt[wid] = __popc(ball);
    __syncthreads();
    int off = 0;
    for (int w = 0; w < wid; w++) off += (int)wcnt[w];
    if (flag) {
        int pos = off + __popc(ball & ((1u << lane) - 1));
        float* p = o + (size_t)pos * 5;
        p[0] = v; p[1] = bx.x; p[2] = bx.y; p[3] = bx.z; p[4] = bx.w;
    }
}

// ===========================================================================
extern "C" void kernel_launch(void* const* d_in, const int* in_sizes, int n_in,
                              void* d_out, int out_size)
{
    const float* loc  = (const float*)d_in[0];
    const float* conf = (const float*)d_in[1];
    const float* dbox = (const float*)d_in[2];
    float* out = (float*)d_out;

    k_softmax_decode<<<BATCH * (NANCH / 128), 256>>>(loc, conf, dbox);
    k_topk_nms<<<BATCH * NC, 256>>>();
    k_global_cutoff<<<BATCH, 256>>>();
    k_write<<<dim3(NCLS, BATCH), 256>>>(out);
}

// round 5
// speedup vs baseline: 1.0173x; 1.0173x over previous
#include <cuda_runtime.h>
#include <cstdint>

#define BATCH 8
#define NANCH 32768
#define NCLS  81
#define NC    80          // foreground classes
#define TOPM  200
#define NMS_TH  0.45f
#define CONF_TH 0.01f
#define NCHUNK  7         // ceil(224/32) bit chunks covering TOPM=200
#define NBIN    2048

// ---------------- scratch (static device globals; no allocations) ----------
__device__ float  g_scores[(size_t)BATCH * NC * NANCH];   // masked probs, [b][c][n]
__device__ float4 g_boxes [(size_t)BATCH * NANCH];        // decoded boxes
__device__ float  g_kept  [(size_t)BATCH * NC * TOPM];    // post-NMS scores (0 if dropped)
__device__ float4 g_cand  [(size_t)BATCH * NC * TOPM];    // candidate boxes
__device__ unsigned long long g_cutoff[BATCH];            // global top-200 composite cutoff

// bin of a score in (CONF_TH, 1): 16-bit float-bit prefix, guaranteed in [0,2048)
__device__ __forceinline__ int score_bin(float v) {
    int b = (int)(__float_as_uint(v) >> 15) - 30720;
    return min(max(b, 0), NBIN - 1);
}

// ===========================================================================
// Kernel 1: softmax over 81 classes + box decode; 2 threads per row.
// Writes transposed masked scores [b][c][n] (0 if below threshold).
// ===========================================================================
__global__ void __launch_bounds__(256)
k_softmax_decode(const float* __restrict__ loc,
                 const float* __restrict__ conf,
                 const float* __restrict__ dbox)
{
    __shared__ float sm[128 * NCLS];     // 41472 B
    __shared__ float sinv[128];

    const int blk = blockIdx.x;                    // B*N/128 blocks
    const int b   = blk / (NANCH / 128);
    const int n0  = (blk % (NANCH / 128)) * 128;
    const int tid = threadIdx.x;

    const float4* src4 = reinterpret_cast<const float4*>(
        conf + ((size_t)b * NANCH + n0) * NCLS);
    float4* sm4 = reinterpret_cast<float4*>(sm);
    for (int i = tid; i < (128 * NCLS) / 4; i += 256)
        sm4[i] = src4[i];

    // box decode - threads 0..127, one row each
    if (tid < 128) {
        const int n = n0 + tid;
        float4 l = reinterpret_cast<const float4*>(loc)[(size_t)b * NANCH + n];
        float4 d = reinterpret_cast<const float4*>(dbox)[n];
        float cx = d.x + l.x * 0.1f * d.z;
        float cy = d.y + l.y * 0.1f * d.w;
        float w  = d.z * expf(l.z * 0.2f);
        float h  = d.w * expf(l.w * 0.2f);
        float x1 = cx - w * 0.5f;
        float y1 = cy - h * 0.5f;
        float4 o;
        o.x = fminf(fmaxf(x1, 0.f), 1.f);
        o.y = fminf(fmaxf(y1, 0.f), 1.f);
        o.z = fminf(fmaxf(x1 + w, 0.f), 1.f);
        o.w = fminf(fmaxf(y1 + h, 0.f), 1.f);
        g_boxes[(size_t)b * NANCH + n] = o;
    }
    __syncthreads();

    // softmax: pair (2r, 2r+1) handles row r; halves = classes [0,41) / [41,81)
    {
        const int r    = tid >> 1;
        const int half = tid & 1;
        const int c0   = half ? 41 : 0;
        const int cn   = half ? 40 : 41;
        float* row = sm + r * NCLS;

        float m = -1e30f;
        #pragma unroll 8
        for (int c = 0; c < cn; c++) m = fmaxf(m, row[c0 + c]);
        m = fmaxf(m, __shfl_xor_sync(0xFFFFFFFFu, m, 1));

        float s = 0.f;
        #pragma unroll 8
        for (int c = 0; c < cn; c++) {
            float e = expf(row[c0 + c] - m);
            row[c0 + c] = e;
            s += e;
        }
        s += __shfl_xor_sync(0xFFFFFFFFu, s, 1);
        if (!half) sinv[r] = 1.0f / s;
    }
    __syncthreads();

    // transposed masked-score writes: coalesced per class
    for (int i = tid; i < 128 * NC; i += 256) {
        const int c  = i >> 7;       // 0..79  (class c+1)
        const int rr = i & 127;
        float p = sm[rr * NCLS + (c + 1)] * sinv[rr];
        g_scores[((size_t)b * NC + c) * NANCH + (n0 + rr)] = (p > CONF_TH) ? p : 0.0f;
    }
}

// ===========================================================================
// Kernel 2: per-(b,class) exact stable top-200. Warp-aggregated (match_any)
// histogram into 2 privatized smem copies, register-resident bin selection,
// single gather pass with uint-threshold, dynamic bitonic sort, bit-matrix NMS.
// ===========================================================================
__global__ void __launch_bounds__(256)
k_topk_nms()
{
    __shared__ unsigned int s_hist[2 * NBIN];      // 2 privatized copies (16KB)
    __shared__ unsigned int psum[256];
    __shared__ unsigned long long buf[2048];
    __shared__ unsigned int s_cnt;
    __shared__ unsigned int s_thr;
    __shared__ int s_g, s_P, s_grp, s_acc;
    __shared__ float4 s_bx[TOPM];
    __shared__ float  s_area[TOPM];
    __shared__ float  s_sc[TOPM];
    __shared__ unsigned int s_sup[TOPM * NCHUNK];  // suppression bit matrix
    __shared__ unsigned int s_act[NCHUNK];
    __shared__ int s_keep[TOPM];

    const int bc   = blockIdx.x;          // b*80 + c
    const int b    = bc / NC;
    const int tid  = threadIdx.x;
    const int lane = tid & 31;
    const float* data = g_scores + (size_t)bc * NANCH;
    const float4* d4  = reinterpret_cast<const float4*>(data);

    // ---- histogram pass: match_any-aggregated atomics, 2 privatized copies ----
    for (int i = tid; i < 2 * NBIN; i += 256) s_hist[i] = 0;
    __syncthreads();
    unsigned int* hcopy = s_hist + ((tid >> 7) << 11);   // halves 0 / 1
    for (int i = tid; i < NANCH / 4; i += 256) {
        float4 v = d4[i];
        const float vs[4] = {v.x, v.y, v.z, v.w};
        #pragma unroll
        for (int j = 0; j < 4; j++) {
            float val = vs[j];
            bool pos = (val > CONF_TH);
            unsigned int act = __ballot_sync(0xFFFFFFFFu, pos);
            if (pos) {
                int bin = score_bin(val);
                unsigned int peers = __match_any_sync(act, bin);
                if (lane == __ffs(peers) - 1)
                    atomicAdd(&hcopy[bin], __popc(peers));
            }
        }
    }
    __syncthreads();

    // ---- combine copies; per-thread 8-bin group sums (register resident) ----
    unsigned int myh[8];
    {
        uint4 a0 = reinterpret_cast<const uint4*>(s_hist)[tid * 2];
        uint4 a1 = reinterpret_cast<const uint4*>(s_hist)[tid * 2 + 1];
        uint4 b0 = reinterpret_cast<const uint4*>(s_hist + NBIN)[tid * 2];
        uint4 b1 = reinterpret_cast<const uint4*>(s_hist + NBIN)[tid * 2 + 1];
        myh[0] = a0.x + b0.x; myh[1] = a0.y + b0.y;
        myh[2] = a0.z + b0.z; myh[3] = a0.w + b0.w;
        myh[4] = a1.x + b1.x; myh[5] = a1.y + b1.y;
        myh[6] = a1.z + b1.z; myh[7] = a1.w + b1.w;
        psum[tid] = myh[0] + myh[1] + myh[2] + myh[3] +
                    myh[4] + myh[5] + myh[6] + myh[7];
    }
    __syncthreads();

    if (tid == 0) {
        int acc = 0, grp = -1;
        for (int t = 255; t >= 0; t--) {
            int c = (int)psum[t];
            if (acc + c >= TOPM) { grp = t; break; }
            acc += c;
        }
        s_grp = grp; s_acc = acc; s_cnt = 0;
        if (grp < 0) s_thr = 0u;   // <200 positives: take all
    }
    __syncthreads();
    const int grp = s_grp;
    if (tid == grp) {
        int acc = s_acc, binq = grp * 8;
        for (int bb = 7; bb >= 0; bb--) {
            int cnt = (int)myh[bb];
            if (acc + cnt >= TOPM) { binq = grp * 8 + bb; break; }
            acc += cnt;
        }
        s_thr = (unsigned int)(binq + 30720) << 15;
    }
    __syncthreads();
    const unsigned int thr = s_thr;

    // ---- gather pass: boundary superset as composite keys ----
    for (int i = tid; i < NANCH / 4; i += 256) {
        float4 v = d4[i];
        const float vs[4] = {v.x, v.y, v.z, v.w};
        #pragma unroll
        for (int j = 0; j < 4; j++) {
            float val = vs[j];
            unsigned int u = __float_as_uint(val);
            if (val > 0.f && u >= thr) {
                unsigned int p = atomicAdd(&s_cnt, 1u);
                if (p < 2048) {
                    unsigned int idx = 4 * i + j;
                    buf[p] = ((unsigned long long)u << 32) |
                             (unsigned long long)(0xFFFFFFFFu - idx);
                }
            }
        }
    }
    __syncthreads();
    if (tid == 0) {
        int g = (int)min(s_cnt, 2048u);
        int P = 256;
        while (P < g) P <<= 1;
        s_g = g; s_P = P;
    }
    __syncthreads();
    const int g = s_g, P = s_P;
    for (int i = tid; i < P; i += 256) if (i >= g) buf[i] = 0ull;
    __syncthreads();

    // ---- bitonic sort, descending, dynamic size P (pow2 in [256,2048]) ----
    for (int k = 2; k <= P; k <<= 1) {
        for (int j = k >> 1; j > 0; j >>= 1) {
            for (int t = tid; t < P; t += 256) {
                int ixj = t ^ j;
                if (ixj > t) {
                    unsigned long long a = buf[t], c2 = buf[ixj];
                    bool dirDesc = ((t & k) == 0);
                    if ((a < c2) == dirDesc) { buf[t] = c2; buf[ixj] = a; }
                }
            }
            __syncthreads();
        }
    }

    // ---- materialize top-200 candidates ----
    bool val_f = false;
    if (tid < TOPM) {
        float sc; float4 bx;
        if (tid < g) {
            unsigned long long cmp = buf[tid];
            sc = __uint_as_float((unsigned int)(cmp >> 32));
            unsigned int idx = 0xFFFFFFFFu - (unsigned int)(cmp & 0xFFFFFFFFull);
            bx = g_boxes[(size_t)b * NANCH + idx];
            val_f = true;
        } else {
            sc = 0.f; bx = make_float4(0.f, 0.f, 0.f, 0.f);
        }
        s_sc[tid]   = sc;
        s_bx[tid]   = bx;
        s_area[tid] = (bx.z - bx.x) * (bx.w - bx.y);
        s_keep[tid] = 0;
    }
    {
        unsigned int bm = __ballot_sync(0xFFFFFFFFu, val_f);
        if (lane == 0 && (tid >> 5) < NCHUNK) s_act[tid >> 5] = bm;
    }
    __syncthreads();

    // ---- suppression bit matrix: bit j of row i set iff !(IoU(i,j) <= th) ----
    for (int task = tid; task < TOPM * NCHUNK; task += 256) {
        const int i     = task / NCHUNK;
        const int chunk = task % NCHUNK;
        const float4 bi = s_bx[i];
        const float  ai = s_area[i];
        unsigned int bits = 0;
        const int jmax = min(32, TOPM - chunk * 32);
        #pragma unroll 4
        for (int bb = 0; bb < jmax; bb++) {
            const int j = chunk * 32 + bb;
            float4 bj = s_bx[j];
            float xx1 = fmaxf(bi.x, bj.x);
            float yy1 = fmaxf(bi.y, bj.y);
            float xx2 = fminf(bi.z, bj.z);
            float yy2 = fminf(bi.w, bj.w);
            float inter = fmaxf(xx2 - xx1, 0.f) * fmaxf(yy2 - yy1, 0.f);
            float uni   = s_area[j] - inter + ai;
            float iou   = inter / uni;
            if (!(iou <= NMS_TH)) bits |= (1u << bb);
        }
        s_sup[task] = bits;
    }
    __syncthreads();

    // ---- greedy scan, single warp, no block barriers ----
    if (tid < 32) {
        unsigned int act = (tid < NCHUNK) ? s_act[tid] : 0u;
        for (int i = 0; i < TOPM; i++) {
            unsigned int owner_act = __shfl_sync(0xFFFFFFFFu, act, i >> 5);
            bool k = (owner_act >> (i & 31)) & 1u;
            if (k) {
                if (tid < NCHUNK) act &= ~s_sup[i * NCHUNK + tid];
                if (tid == 0) s_keep[i] = 1;
            }
        }
    }
    __syncthreads();

    if (tid < TOPM) {
        g_kept[(size_t)bc * TOPM + tid] = s_keep[tid] ? s_sc[tid] : 0.f;
        g_cand[(size_t)bc * TOPM + tid] = s_bx[tid];
    }
}

// ===========================================================================
// Kernel 3: per-batch global top-200 composite cutoff over 16000 kept scores.
// ===========================================================================
__global__ void __launch_bounds__(256)
k_global_cutoff()
{
    __shared__ unsigned int hist[NBIN];
    __shared__ unsigned int psum[256];
    __shared__ unsigned long long buf[2048];
    __shared__ unsigned int s_cnt;
    __shared__ int s_bin, s_g, s_P;

    const int b    = blockIdx.x;
    const int tid  = threadIdx.x;
    const int lane = tid & 31;
    const int NTOT = NC * TOPM;          // 16000
    const float* data = g_kept + (size_t)b * NTOT;
    const float4* d4  = reinterpret_cast<const float4*>(data);

    for (int i = tid; i < NBIN; i += 256) hist[i] = 0;
    __syncthreads();
    for (int i = tid; i < NTOT / 4; i += 256) {
        float4 v = d4[i];
        const float vs[4] = {v.x, v.y, v.z, v.w};
        #pragma unroll
        for (int j = 0; j < 4; j++) {
            float val = vs[j];
            bool pos = (val > 0.f);
            unsigned int act = __ballot_sync(0xFFFFFFFFu, pos);
            if (pos) {
                int bin = score_bin(val);
                unsigned int peers = __match_any_sync(act, bin);
                if (lane == __ffs(peers) - 1)
                    atomicAdd(&hist[bin], __popc(peers));
            }
        }
    }
    __syncthreads();
    { unsigned int s = 0;
      #pragma unroll
      for (int j = 0; j < 8; j++) s += hist[tid * 8 + j];
      psum[tid] = s; }
    __syncthreads();
    if (tid == 0) {
        int acc = 0, binq = -1;
        for (int t = 255; t >= 0; t--) {
            if (acc + (int)psum[t] >= TOPM) {
                for (int bb = t * 8 + 7; bb >= t * 8; bb--) {
                    int cnt = (int)hist[bb];
                    if (acc + cnt >= TOPM) { binq = bb; break; }
                    acc += cnt;
                }
                break;
            }
            acc += (int)psum[t];
        }
        s_bin = binq;
        s_cnt = 0;
    }
    __syncthreads();
    const int binq = s_bin;

    if (binq < 0) {                      // fewer than 200 positives: keep all
        if (tid == 0) g_cutoff[b] = 0ull;
        return;
    }
    const unsigned int thr = (unsigned int)(binq + 30720) << 15;

    for (int i = tid; i < NTOT / 4; i += 256) {
        float4 v = d4[i];
        const float vs[4] = {v.x, v.y, v.z, v.w};
        #pragma unroll
        for (int j = 0; j < 4; j++) {
            float val = vs[j];
            unsigned int u = __float_as_uint(val);
            if (val > 0.f && u >= thr) {
                unsigned int p = atomicAdd(&s_cnt, 1u);
                if (p < 2048) {
                    unsigned int idx = 4 * i + j;
                    buf[p] = ((unsigned long long)u << 32) |
                             (unsigned long long)(0xFFFFFFFFu - idx);
                }
            }
        }
    }
    __syncthreads();
    if (tid == 0) {
        int g = (int)min(s_cnt, 2048u);
        int P = 256;
        while (P < g) P <<= 1;
        s_g = g; s_P = P;
    }
    __syncthreads();
    const int g = s_g, P = s_P;
    for (int i = tid; i < P; i += 256) if (i >= g) buf[i] = 0ull;
    __syncthreads();

    for (int k = 2; k <= P; k <<= 1) {
        for (int j = k >> 1; j > 0; j >>= 1) {
            for (int t = tid; t < P; t += 256) {
                int ixj = t ^ j;
                if (ixj > t) {
                    unsigned long long a = buf[t], c2 = buf[ixj];
                    bool dirDesc = ((t & k) == 0);
                    if ((a < c2) == dirDesc) { buf[t] = c2; buf[ixj] = a; }
                }
            }
            __syncthreads();
        }
    }

    if (tid == 0)
        g_cutoff[b] = buf[TOPM - 1];
}

// ===========================================================================
// Kernel 4: output writer — zero everything, then compact survivors to front.
// ===========================================================================
__global__ void __launch_bounds__(256)
k_write(float* __restrict__ out)
{
    __shared__ unsigned int wcnt[8];
    const int c   = blockIdx.x;   // 0..80
    const int b   = blockIdx.y;
    const int tid = threadIdx.x;

    float* o = out + ((size_t)(b * NCLS + c)) * TOPM * 5;
    for (int i = tid; i < TOPM * 5; i += 256) o[i] = 0.f;
    if (c == 0) return;
    __syncthreads();

    const int c80 = c - 1;
    const size_t base = ((size_t)b * NC + c80) * TOPM;
    const unsigned long long cut = g_cutoff[b];

    float v = 0.f; bool flag = false; float4 bx = make_float4(0.f, 0.f, 0.f, 0.f);
    if (tid < TOPM) {
        v = g_kept[base + tid];
        if (v > 0.f) {
            unsigned long long comp =
                ((unsigned long long)__float_as_uint(v) << 32) |
                (unsigned long long)(0xFFFFFFFFu - (unsigned int)(c80 * TOPM + tid));
            flag = (comp >= cut);
        }
        if (flag) bx = g_cand[base + tid];
    }
    unsigned int ball = __ballot_sync(0xFFFFFFFFu, flag);
    const int wid = tid >> 5, lane = tid & 31;
    if (lane == 0) wcnt[wid] = __popc(ball);
    __syncthreads();
    int off = 0;
    for (int w = 0; w < wid; w++) off += (int)wcnt[w];
    if (flag) {
        int pos = off + __popc(ball & ((1u << lane) - 1));
        float* p = o + (size_t)pos * 5;
        p[0] = v; p[1] = bx.x; p[2] = bx.y; p[3] = bx.z; p[4] = bx.w;
    }
}

// ===========================================================================
extern "C" void kernel_launch(void* const* d_in, const int* in_sizes, int n_in,
                              void* d_out, int out_size)
{
    const float* loc  = (const float*)d_in[0];
    const float* conf = (const float*)d_in[1];
    const float* dbox = (const float*)d_in[2];
    float* out = (float*)d_out;

    k_softmax_decode<<<BATCH * (NANCH / 128), 256>>>(loc, conf, dbox);
    k_topk_nms<<<BATCH * NC, 256>>>();
    k_global_cutoff<<<BATCH, 256>>>();
    k_write<<<dim3(NCLS, BATCH), 256>>>(out);
}

// round 6
// speedup vs baseline: 1.2436x; 1.2225x over previous
#include <cuda_runtime.h>
#include <cstdint>

#define BATCH 8
#define NANCH 32768
#define NCLS  81
#define NC    80
#define TOPM  200
#define NMS_TH  0.45f
#define CONF_TH 0.01f
#define NCHUNK  7
#define NBIN    2048

__device__ float  g_scores[(size_t)BATCH * NC * NANCH];
__device__ float4 g_boxes [(size_t)BATCH * NANCH];
__device__ float  g_kept  [(size_t)BATCH * NC * TOPM];
__device__ float4 g_cand  [(size_t)BATCH * NC * TOPM];
__device__ unsigned long long g_cutoff[BATCH];

__device__ __forceinline__ int score_bin(float v) {
    int b = (int)(__float_as_uint(v) >> 15) - 30720;
    return min(max(b, 0), NBIN - 1);
}

// ---------------- packed f32x2 helpers (sm_103a) ----------------
__device__ __forceinline__ unsigned long long pk2(float lo, float hi) {
    unsigned long long d;
    asm("mov.b64 %0, {%1, %2};" : "=l"(d) : "f"(lo), "f"(hi));
    return d;
}
__device__ __forceinline__ void unpk2(unsigned long long v, float& lo, float& hi) {
    asm("mov.b64 {%0, %1}, %2;" : "=f"(lo), "=f"(hi) : "l"(v));
}
__device__ __forceinline__ unsigned long long fma2(unsigned long long a,
                                                   unsigned long long b,
                                                   unsigned long long c) {
    unsigned long long d;
    asm("fma.rn.f32x2 %0, %1, %2, %3;" : "=l"(d) : "l"(a), "l"(b), "l"(c));
    return d;
}
__device__ __forceinline__ unsigned long long add2(unsigned long long a,
                                                   unsigned long long b) {
    unsigned long long d;
    asm("add.rn.f32x2 %0, %1, %2;" : "=l"(d) : "l"(a), "l"(b));
    return d;
}
__device__ __forceinline__ unsigned long long mul2(unsigned long long a,
                                                   unsigned long long b) {
    unsigned long long d;
    asm("mul.rn.f32x2 %0, %1, %2;" : "=l"(d) : "l"(a), "l"(b));
    return d;
}

// ===========================================================================
// Kernel 1: softmax + box decode. 2 threads/row. Exps split across pipes:
// per half, first chunk of classes via MUFU exp2f, last 18 via packed
// f32x2 degree-7 polynomial on the FMA pipe (fixed per class).
// ===========================================================================
__global__ void __launch_bounds__(256)
k_softmax_decode(const float* __restrict__ loc,
                 const float* __restrict__ conf,
                 const float* __restrict__ dbox)
{
    __shared__ float sm[128 * NCLS];
    __shared__ float sinv[128];

    const int blk = blockIdx.x;
    const int b   = blk / (NANCH / 128);
    const int n0  = (blk % (NANCH / 128)) * 128;
    const int tid = threadIdx.x;

    const float4* src4 = reinterpret_cast<const float4*>(
        conf + ((size_t)b * NANCH + n0) * NCLS);
    float4* sm4 = reinterpret_cast<float4*>(sm);
    for (int i = tid; i < (128 * NCLS) / 4; i += 256)
        sm4[i] = src4[i];

    if (tid < 128) {
        const int n = n0 + tid;
        float4 l = reinterpret_cast<const float4*>(loc)[(size_t)b * NANCH + n];
        float4 d = reinterpret_cast<const float4*>(dbox)[n];
        float cx = d.x + l.x * 0.1f * d.z;
        float cy = d.y + l.y * 0.1f * d.w;
        float w  = d.z * expf(l.z * 0.2f);
        float h  = d.w * expf(l.w * 0.2f);
        float x1 = cx - w * 0.5f;
        float y1 = cy - h * 0.5f;
        float4 o;
        o.x = fminf(fmaxf(x1, 0.f), 1.f);
        o.y = fminf(fmaxf(y1, 0.f), 1.f);
        o.z = fminf(fmaxf(x1 + w, 0.f), 1.f);
        o.w = fminf(fmaxf(y1 + h, 0.f), 1.f);
        g_boxes[(size_t)b * NANCH + n] = o;
    }
    __syncthreads();

    {
        const int r    = tid >> 1;
        const int half = tid & 1;
        const int c0   = half ? 41 : 0;     // class range start
        const int cn   = half ? 40 : 41;    // count (poly = last 18 of each)
        const int nmu  = cn - 18;           // 23 / 22 mufu classes
        float* row = sm + r * NCLS;

        float m = -1e30f;
        #pragma unroll 8
        for (int c = 0; c < cn; c++) m = fmaxf(m, row[c0 + c]);
        m = fmaxf(m, __shfl_xor_sync(0xFFFFFFFFu, m, 1));

        const float L2E = 1.44269504088896340736f;
        const float mLn = -m * L2E;
        float s = 0.f;

        // MUFU path: e = exp2f((x-m)*log2e)
        #pragma unroll 8
        for (int c = 0; c < nmu; c++) {
            float e = exp2f(fmaf(row[c0 + c], L2E, mLn));
            row[c0 + c] = e;
            s += e;
        }

        // FMA-pipe path: packed f32x2, 9 pairs = 18 classes
        const unsigned long long L2E2 = pk2(L2E, L2E);
        const unsigned long long ML2  = pk2(mLn, mLn);
        const unsigned long long MAG2 = pk2(12582912.0f, 12582912.0f);
        const unsigned long long NMG2 = pk2(-12582912.0f, -12582912.0f);
        const unsigned long long NE12 = pk2(-1.0f, -1.0f);
        const unsigned long long C7 = pk2(1.5252734e-5f, 1.5252734e-5f);
        const unsigned long long C6 = pk2(1.5403530e-4f, 1.5403530e-4f);
        const unsigned long long C5 = pk2(1.3333558e-3f, 1.3333558e-3f);
        const unsigned long long C4 = pk2(9.6181291e-3f, 9.6181291e-3f);
        const unsigned long long C3 = pk2(5.5504109e-2f, 5.5504109e-2f);
        const unsigned long long C2 = pk2(2.4022651e-1f, 2.4022651e-1f);
        const unsigned long long C1 = pk2(6.9314718e-1f, 6.9314718e-1f);
        const unsigned long long ONE2 = pk2(1.0f, 1.0f);

        unsigned long long s2 = pk2(0.f, 0.f);
        #pragma unroll
        for (int j = 0; j < 18; j += 2) {
            const int c = c0 + nmu + j;
            unsigned long long X = pk2(row[c], row[c + 1]);
            unsigned long long T = fma2(X, L2E2, ML2);
            unsigned long long R = add2(T, MAG2);          // round(t) in low bits
            unsigned long long FI = add2(R, NMG2);         // round(t) as float
            unsigned long long F  = fma2(FI, NE12, T);     // f = t - round(t)
            unsigned long long P  = fma2(C7, F, C6);
            P = fma2(P, F, C5);
            P = fma2(P, F, C4);
            P = fma2(P, F, C3);
            P = fma2(P, F, C2);
            P = fma2(P, F, C1);
            P = fma2(P, F, ONE2);
            unsigned int rlo = (unsigned int)R;
            unsigned int rhi = (unsigned int)(R >> 32);
            unsigned int slo = ((rlo - 0x4B400000u) << 23) + 0x3F800000u;
            unsigned int shi = ((rhi - 0x4B400000u) << 23) + 0x3F800000u;
            unsigned long long SC = ((unsigned long long)shi << 32) | slo;
            unsigned long long E  = mul2(P, SC);
            float elo, ehi;
            unpk2(E, elo, ehi);
            row[c]     = elo;
            row[c + 1] = ehi;
            s2 = add2(s2, E);
        }
        {
            float alo, ahi;
            unpk2(s2, alo, ahi);
            s += alo + ahi;
        }
        s += __shfl_xor_sync(0xFFFFFFFFu, s, 1);
        if (!half) sinv[r] = 1.0f / s;
    }
    __syncthreads();

    // transposed masked-score writes, float4 vectorized
    for (int i = tid; i < 32 * NC; i += 256) {
        const int c   = i >> 5;          // 0..79  (class c+1)
        const int rr4 = (i & 31) * 4;
        float4 p;
        float i0 = sinv[rr4], i1 = sinv[rr4+1], i2 = sinv[rr4+2], i3 = sinv[rr4+3];
        p.x = sm[(rr4    ) * NCLS + (c + 1)] * i0;
        p.y = sm[(rr4 + 1) * NCLS + (c + 1)] * i1;
        p.z = sm[(rr4 + 2) * NCLS + (c + 1)] * i2;
        p.w = sm[(rr4 + 3) * NCLS + (c + 1)] * i3;
        p.x = (p.x > CONF_TH) ? p.x : 0.f;
        p.y = (p.y > CONF_TH) ? p.y : 0.f;
        p.z = (p.z > CONF_TH) ? p.z : 0.f;
        p.w = (p.w > CONF_TH) ? p.w : 0.f;
        reinterpret_cast<float4*>(
            g_scores + ((size_t)b * NC + c) * NANCH + n0)[i & 31] = p;
    }
}

// ===========================================================================
// Kernel 2: per-(b,class) exact stable top-200 (single-pass 16-bit radix
// select + dynamic bitonic) fused with bit-matrix NMS.   (R2 version)
// ===========================================================================
__global__ void __launch_bounds__(256)
k_topk_nms()
{
    __shared__ unsigned int hist[NBIN];
    __shared__ unsigned int psum[256];
    __shared__ unsigned long long buf[2048];
    __shared__ unsigned int s_cnt;
    __shared__ int s_bin, s_g, s_P;
    __shared__ float4 s_bx[TOPM];
    __shared__ float  s_area[TOPM];
    __shared__ float  s_sc[TOPM];
    __shared__ unsigned int s_sup[TOPM * NCHUNK];
    __shared__ unsigned int s_act[NCHUNK];
    __shared__ int s_keep[TOPM];

    const int bc  = blockIdx.x;
    const int b   = bc / NC;
    const int tid = threadIdx.x;
    const float* data = g_scores + (size_t)bc * NANCH;
    const float4* d4  = reinterpret_cast<const float4*>(data);

    for (int i = tid; i < NBIN; i += 256) hist[i] = 0;
    __syncthreads();
    for (int i = tid; i < NANCH / 4; i += 256) {
        float4 v = d4[i];
        if (v.x > CONF_TH) atomicAdd(&hist[score_bin(v.x)], 1u);
        if (v.y > CONF_TH) atomicAdd(&hist[score_bin(v.y)], 1u);
        if (v.z > CONF_TH) atomicAdd(&hist[score_bin(v.z)], 1u);
        if (v.w > CONF_TH) atomicAdd(&hist[score_bin(v.w)], 1u);
    }
    __syncthreads();
    { unsigned int s = 0;
      #pragma unroll
      for (int j = 0; j < 8; j++) s += hist[tid * 8 + j];
      psum[tid] = s; }
    __syncthreads();
    if (tid == 0) {
        int acc = 0, binq = -1;
        for (int t = 255; t >= 0; t--) {
            if (acc + (int)psum[t] >= TOPM) {
                for (int bb = t * 8 + 7; bb >= t * 8; bb--) {
                    int cnt = (int)hist[bb];
                    if (acc + cnt >= TOPM) { binq = bb; break; }
                    acc += cnt;
                }
                break;
            }
            acc += (int)psum[t];
        }
        s_bin = binq;
        s_cnt = 0;
    }
    __syncthreads();
    const int binq = s_bin;
    const unsigned int thr = (binq < 0) ? 0u : ((unsigned int)(binq + 30720) << 15);

    for (int i = tid; i < NANCH / 4; i += 256) {
        float4 v = d4[i];
        const float vs[4] = {v.x, v.y, v.z, v.w};
        #pragma unroll
        for (int j = 0; j < 4; j++) {
            float val = vs[j];
            unsigned int u = __float_as_uint(val);
            if (val > 0.f && u >= thr) {
                unsigned int p = atomicAdd(&s_cnt, 1u);
                if (p < 2048) {
                    unsigned int idx = 4 * i + j;
                    buf[p] = ((unsigned long long)u << 32) |
                             (unsigned long long)(0xFFFFFFFFu - idx);
                }
            }
        }
    }
    __syncthreads();
    if (tid == 0) {
        int g = (int)min(s_cnt, 2048u);
        int P = 256;
        while (P < g) P <<= 1;
        s_g = g; s_P = P;
    }
    __syncthreads();
    const int g = s_g, P = s_P;
    for (int i = tid; i < P; i += 256) if (i >= g) buf[i] = 0ull;
    __syncthreads();

    for (int k = 2; k <= P; k <<= 1) {
        for (int j = k >> 1; j > 0; j >>= 1) {
            for (int t = tid; t < P; t += 256) {
                int ixj = t ^ j;
                if (ixj > t) {
                    unsigned long long a = buf[t], c2 = buf[ixj];
                    bool dirDesc = ((t & k) == 0);
                    if ((a < c2) == dirDesc) { buf[t] = c2; buf[ixj] = a; }
                }
            }
            __syncthreads();
        }
    }

    bool val_f = false;
    if (tid < TOPM) {
        float sc; float4 bx;
        if (tid < g) {
            unsigned long long cmp = buf[tid];
            sc = __uint_as_float((unsigned int)(cmp >> 32));
            unsigned int idx = 0xFFFFFFFFu - (unsigned int)(cmp & 0xFFFFFFFFull);
            bx = g_boxes[(size_t)b * NANCH + idx];
            val_f = true;
        } else {
            sc = 0.f; bx = make_float4(0.f, 0.f, 0.f, 0.f);
        }
        s_sc[tid]   = sc;
        s_bx[tid]   = bx;
        s_area[tid] = (bx.z - bx.x) * (bx.w - bx.y);
        s_keep[tid] = 0;
    }
    {
        unsigned int bm = __ballot_sync(0xFFFFFFFFu, val_f);
        if ((tid & 31) == 0 && (tid >> 5) < NCHUNK) s_act[tid >> 5] = bm;
    }
    __syncthreads();

    for (int task = tid; task < TOPM * NCHUNK; task += 256) {
        const int i     = task / NCHUNK;
        const int chunk = task % NCHUNK;
        const float4 bi = s_bx[i];
        const float  ai = s_area[i];
        unsigned int bits = 0;
        const int jmax = min(32, TOPM - chunk * 32);
        #pragma unroll 4
        for (int bb = 0; bb < jmax; bb++) {
            const int j = chunk * 32 + bb;
            float4 bj = s_bx[j];
            float xx1 = fmaxf(bi.x, bj.x);
            float yy1 = fmaxf(bi.y, bj.y);
            float xx2 = fminf(bi.z, bj.z);
            float yy2 = fminf(bi.w, bj.w);
            float inter = fmaxf(xx2 - xx1, 0.f) * fmaxf(yy2 - yy1, 0.f);
            float uni   = s_area[j] - inter + ai;
            float iou   = inter / uni;
            if (!(iou <= NMS_TH)) bits |= (1u << bb);
        }
        s_sup[task] = bits;
    }
    __syncthreads();

    if (tid < 32) {
        unsigned int act = (tid < NCHUNK) ? s_act[tid] : 0u;
        for (int i = 0; i < TOPM; i++) {
            unsigned int owner_act = __shfl_sync(0xFFFFFFFFu, act, i >> 5);
            bool k = (owner_act >> (i & 31)) & 1u;
            if (k) {
                if (tid < NCHUNK) act &= ~s_sup[i * NCHUNK + tid];
                if (tid == 0) s_keep[i] = 1;
            }
        }
    }
    __syncthreads();

    if (tid < TOPM) {
        g_kept[(size_t)bc * TOPM + tid] = s_keep[tid] ? s_sc[tid] : 0.f;
        g_cand[(size_t)bc * TOPM + tid] = s_bx[tid];
    }
}

// ===========================================================================
// Kernel 3: per-batch global top-200 composite cutoff.   (R2 version)
// ===========================================================================
__global__ void __launch_bounds__(256)
k_global_cutoff()
{
    __shared__ unsigned int hist[NBIN];
    __shared__ unsigned int psum[256];
    __shared__ unsigned long long buf[2048];
    __shared__ unsigned int s_cnt;
    __shared__ int s_bin, s_g, s_P;

    const int b   = blockIdx.x;
    const int tid = threadIdx.x;
    const int NTOT = NC * TOPM;
    const float* data = g_kept + (size_t)b * NTOT;
    const float4* d4  = reinterpret_cast<const float4*>(data);

    for (int i = tid; i < NBIN; i += 256) hist[i] = 0;
    __syncthreads();
    for (int i = tid; i < NTOT / 4; i += 256) {
        float4 v = d4[i];
        if (v.x > 0.f) atomicAdd(&hist[score_bin(v.x)], 1u);
        if (v.y > 0.f) atomicAdd(&hist[score_bin(v.y)], 1u);
        if (v.z > 0.f) atomicAdd(&hist[score_bin(v.z)], 1u);
        if (v.w > 0.f) atomicAdd(&hist[score_bin(v.w)], 1u);
    }
    __syncthreads();
    { unsigned int s = 0;
      #pragma unroll
      for (int j = 0; j < 8; j++) s += hist[tid * 8 + j];
      psum[tid] = s; }
    __syncthreads();
    if (tid == 0) {
        int acc = 0, binq = -1;
        for (int t = 255; t >= 0; t--) {
            if (acc + (int)psum[t] >= TOPM) {
                for (int bb = t * 8 + 7; bb >= t * 8; bb--) {
                    int cnt = (int)hist[bb];
                    if (acc + cnt >= TOPM) { binq = bb; break; }
                    acc += cnt;
                }
                break;
            }
            acc += (int)psum[t];
        }
        s_bin = binq;
        s_cnt = 0;
    }
    __syncthreads();
    const int binq = s_bin;

    if (binq < 0) {
        if (tid == 0) g_cutoff[b] = 0ull;
        return;
    }
    const unsigned int thr = (unsigned int)(binq + 30720) << 15;

    for (int i = tid; i < NTOT / 4; i += 256) {
        float4 v = d4[i];
        const float vs[4] = {v.x, v.y, v.z, v.w};
        #pragma unroll
        for (int j = 0; j < 4; j++) {
            float val = vs[j];
            unsigned int u = __float_as_uint(val);
            if (val > 0.f && u >= thr) {
                unsigned int p = atomicAdd(&s_cnt, 1u);
                if (p < 2048) {
                    unsigned int idx = 4 * i + j;
                    buf[p] = ((unsigned long long)u << 32) |
                             (unsigned long long)(0xFFFFFFFFu - idx);
                }
            }
        }
    }
    __syncthreads();
    if (tid == 0) {
        int g = (int)min(s_cnt, 2048u);
        int P = 256;
        while (P < g) P <<= 1;
        s_g = g; s_P = P;
    }
    __syncthreads();
    const int g = s_g, P = s_P;
    for (int i = tid; i < P; i += 256) if (i >= g) buf[i] = 0ull;
    __syncthreads();

    for (int k = 2; k <= P; k <<= 1) {
        for (int j = k >> 1; j > 0; j >>= 1) {
            for (int t = tid; t < P; t += 256) {
                int ixj = t ^ j;
                if (ixj > t) {
                    unsigned long long a = buf[t], c2 = buf[ixj];
                    bool dirDesc = ((t & k) == 0);
                    if ((a < c2) == dirDesc) { buf[t] = c2; buf[ixj] = a; }
                }
            }
            __syncthreads();
        }
    }

    if (tid == 0)
        g_cutoff[b] = buf[TOPM - 1];
}

// ===========================================================================
// Kernel 4: output writer.   (R2 version)
// ===========================================================================
__global__ void __launch_bounds__(256)
k_write(float* __restrict__ out)
{
    __shared__ unsigned int wcnt[8];
    const int c   = blockIdx.x;
    const int b   = blockIdx.y;
    const int tid = threadIdx.x;

    float* o = out + ((size_t)(b * NCLS + c)) * TOPM * 5;
    for (int i = tid; i < TOPM * 5; i += 256) o[i] = 0.f;
    if (c == 0) return;
    __syncthreads();

    const int c80 = c - 1;
    const size_t base = ((size_t)b * NC + c80) * TOPM;
    const unsigned long long cut = g_cutoff[b];

    float v = 0.f; bool flag = false; float4 bx = make_float4(0.f, 0.f, 0.f, 0.f);
    if (tid < TOPM) {
        v = g_kept[base + tid];
        if (v > 0.f) {
            unsigned long long comp =
                ((unsigned long long)__float_as_uint(v) << 32) |
                (unsigned long long)(0xFFFFFFFFu - (unsigned int)(c80 * TOPM + tid));
            flag = (comp >= cut);
        }
        if (flag) bx = g_cand[base + tid];
    }
    unsigned int ball = __ballot_sync(0xFFFFFFFFu, flag);
    const int wid = tid >> 5, lane = tid & 31;
    if (lane == 0) wcnt[wid] = __popc(ball);
    __syncthreads();
    int off = 0;
    for (int w = 0; w < wid; w++) off += (int)wcnt[w];
    if (flag) {
        int pos = off + __popc(ball & ((1u << lane) - 1));
        float* p = o + (size_t)pos * 5;
        p[0] = v; p[1] = bx.x; p[2] = bx.y; p[3] = bx.z; p[4] = bx.w;
    }
}

// ===========================================================================
extern "C" void kernel_launch(void* const* d_in, const int* in_sizes, int n_in,
                              void* d_out, int out_size)
{
    const float* loc  = (const float*)d_in[0];
    const float* conf = (const float*)d_in[1];
    const float* dbox = (const float*)d_in[2];
    float* out = (float*)d_out;

    k_softmax_decode<<<BATCH * (NANCH / 128), 256>>>(loc, conf, dbox);
    k_topk_nms<<<BATCH * NC, 256>>>();
    k_global_cutoff<<<BATCH, 256>>>();
    k_write<<<dim3(NCLS, BATCH), 256>>>(out);
}